// round 12
// baseline (speedup 1.0000x reference)
#include <cuda_runtime.h>

#define NUM_BINS 15
#define NMC_CAP  10240
#define QB_CAP   80
#define DSPLIT   16
#define TILE     512          /* points per tile */
#define TPAIRS   (TILE / 2)   /* 256 pairs, compile-time trip count */
#define HTR_B    16
#define HTE_B    8

#define STEP (1.0f / 15.0f)
#define C2   (1.4426950408889634f / 0.18f)   /* log2e / (2*BW*BW) */
#define KN   (0.5654866776461628f)           /* 2*pi*BW*BW */

typedef unsigned long long ull;

// ---------------- device scratch ----------------
__device__ int    g_hist_tr_p[HTR_B][NUM_BINS];
__device__ int    g_hist_te_p[HTE_B][NUM_BINS];
__device__ int    g_correct;
__device__ int    g_qcnt[NUM_BINS];
__device__ float2 g_q[NUM_BINS * NMC_CAP];
// layout: [ (z*3 + ph)*NUM_BINS + bin ] * NMC_CAP + qi   (qi fastest: coalesced)
__device__ float  g_ssum[(size_t)DSPLIT * 3 * NUM_BINS * NMC_CAP];  // ~29 MB
__device__ float  g_part[NUM_BINS * QB_CAP];

// ---------------- packed helpers ----------------
#define ADD2(d, a, b)    asm("add.rn.f32x2 %0, %1, %2;"      : "=l"(d) : "l"(a), "l"(b))
#define FMA2(d, a, b, c) asm("fma.rn.f32x2 %0, %1, %2, %3;"  : "=l"(d) : "l"(a), "l"(b), "l"(c))
#define PK2(d, lo, hi)   asm("mov.b64 %0, {%1, %2};"         : "=l"(d) : "f"(lo), "f"(hi))
#define UPK2(lo, hi, s)  asm("mov.b64 {%0, %1}, %2;"         : "=f"(lo), "=f"(hi) : "l"(s))

__device__ __forceinline__ float ex2_approx(float x) {
    float r;
    asm("ex2.approx.ftz.f32 %0, %1;" : "=f"(r) : "f"(x));
    return r;
}

// hat_s = max softmax(x@W + b); membership in bin's [lo,hi] (inclusive)
__device__ __forceinline__ bool pass_bin(float qx, float qy,
                                         const float* __restrict__ W,
                                         const float* __restrict__ bv,
                                         int bin) {
    float l[10];
    float lmax = -1e30f;
    #pragma unroll
    for (int c = 0; c < 10; c++) {
        l[c] = fmaf(qx, W[c], fmaf(qy, W[10 + c], bv[c]));
        lmax = fmaxf(lmax, l[c]);
    }
    float s = 0.f;
    #pragma unroll
    for (int c = 0; c < 10; c++) s += __expf(l[c] - lmax);
    float hs = 1.f / s;
    float lo = bin * STEP;
    float hi = (bin + 1) * STEP;
    return (hs >= lo) && (hs <= hi);
}

// ---------------- K1: fused filter + hist partials + correct ----------------
__global__ void __launch_bounds__(1024) prep_kernel(
    const float* __restrict__ mc, const float* __restrict__ W,
    const float* __restrict__ bv,
    const float* __restrict__ trp, const float* __restrict__ tep,
    const int* __restrict__ y, const int* __restrict__ pred,
    int NMC, int NTR, int NTE, int B)
{
    const int part = blockIdx.x;
    const int tid  = threadIdx.x;

    if (part < NUM_BINS) {
        __shared__ int wtot[32];
        __shared__ int wbase[32];
        __shared__ int runbase;
        const int bin  = part;
        const int lane = tid & 31;
        const int wid  = tid >> 5;
        if (tid == 0) runbase = 0;
        __syncthreads();

        for (int base = 0; base < NMC; base += 1024) {
            int qi = base + tid;
            bool p = false;
            float qx = 0.f, qy = 0.f;
            if (qi < NMC) {
                qx = mc[(size_t)(bin * NMC + qi) * 2 + 0];
                qy = mc[(size_t)(bin * NMC + qi) * 2 + 1];
                p = pass_bin(qx, qy, W, bv, bin);
            }
            unsigned mask = __ballot_sync(0xffffffffu, p);
            int off = __popc(mask & ((1u << lane) - 1u));
            if (lane == 0) wtot[wid] = __popc(mask);
            __syncthreads();
            if (tid == 0) {
                int r = runbase;
                #pragma unroll
                for (int w = 0; w < 32; w++) { wbase[w] = r; r += wtot[w]; }
                runbase = r;
            }
            __syncthreads();
            if (p)
                g_q[bin * NMC_CAP + wbase[wid] + off] = make_float2(qx, qy);
            __syncthreads();
        }
        if (tid == 0) g_qcnt[bin] = runbase;
    } else if (part < NUM_BINS + HTR_B + HTE_B) {
        __shared__ int sh[NUM_BINS];
        if (tid < NUM_BINS) sh[tid] = 0;
        __syncthreads();
        bool is_tr = (part < NUM_BINS + HTR_B);
        const float* src = is_tr ? trp : tep;
        int n  = is_tr ? NTR : NTE;
        int nb = is_tr ? HTR_B : HTE_B;
        int pb = is_tr ? (part - NUM_BINS) : (part - NUM_BINS - HTR_B);
        for (int i = pb * 1024 + tid; i < n; i += nb * 1024) {
            float p = src[i];
            int bx = (int)ceilf(p * 15.f) - 1;
            bx = min(14, max(0, bx));
            if (!(p > bx * STEP && p <= (bx + 1) * STEP)) {
                if (p <= bx * STEP) bx--; else bx++;
            }
            if (bx >= 0 && bx < NUM_BINS && p > bx * STEP && p <= (bx + 1) * STEP)
                atomicAdd(&sh[bx], 1);
        }
        __syncthreads();
        if (tid < NUM_BINS) {
            if (is_tr) g_hist_tr_p[pb][tid] = sh[tid];
            else       g_hist_te_p[pb][tid] = sh[tid];
        }
    } else {
        __shared__ int red[1024];
        int c = 0;
        for (int i = tid; i < B; i += 1024)
            c += (y[i] == pred[i]) ? 1 : 0;
        red[tid] = c; __syncthreads();
        for (int s = 512; s > 0; s >>= 1) {
            if (tid < s) red[tid] += red[tid + s];
            __syncthreads();
        }
        if (tid == 0) g_correct = red[0];
    }
}

// ---------------- K2: KDE main (f16x2 EX2, constant-trip sentinel-padded) ----
__global__ void __launch_bounds__(128) main_kernel(
    const float* __restrict__ trx, const float* __restrict__ tex,
    const float* __restrict__ bx,
    const int* __restrict__ y, const int* __restrict__ pred,
    int NTRX, int NTEX, int B)
{
    __shared__ __align__(16) unsigned char sraw[TPAIRS * 16 + TPAIRS * 8];
    float4* sP = (float4*)sraw;                    // [TPAIRS] (cmx0,cmx1,cmy0,cmy1)
    float2* sZ = (float2*)(sraw + TPAIRS * 16);    // [TPAIRS] (z0,z1)
    float4* sd = (float4*)sraw;                    // phase-2 view

    const int bin = blockIdx.y;
    const int z   = blockIdx.z;
    const int cnt = g_qcnt[bin];
    if ((int)(blockIdx.x * 128) >= cnt) return;

    const int  qi  = blockIdx.x * 128 + threadIdx.x;
    const bool act = qi < cnt;
    float2 q = act ? g_q[bin * NMC_CAP + qi] : make_float2(0.f, 0.f);

    const float Cm = 2.f * C2;
    const float A  = -C2 * (q.x * q.x + q.y * q.y);
    ull qx2, qy2, A2;
    PK2(qx2, q.x, q.x);
    PK2(qy2, q.y, q.y);
    PK2(A2,  A,   A);

    // ---- phases 0/1: unweighted KDE, f16x2 EX2, 256-trip tiles ----
    #pragma unroll 1
    for (int ph = 0; ph < 2; ph++) {
        const float* src = (ph == 0) ? trx : tex;
        const int    n   = (ph == 0) ? NTRX : NTEX;
        const int np = n / 2;
        const int p0 = (int)(((long long)z * np) / DSPLIT);
        const int p1 = (int)(((long long)(z + 1) * np) / DSPLIT);
        float a0 = 0.f, a1 = 0.f;

        for (int basep = p0; basep < p1; basep += TPAIRS) {
            // fill with sentinel padding: exactly 2 iterations per thread
            #pragma unroll
            for (int k = 0; k < TPAIRS / 128; k++) {
                int jp = k * 128 + threadIdx.x;
                int gp = basep + jp;
                if (gp < p1) {
                    float4 v = ((const float4*)src)[gp];   // (x0,y0,x1,y1)
                    sP[jp] = make_float4(Cm * v.x, Cm * v.z, Cm * v.y, Cm * v.w);
                    sZ[jp] = make_float2(-C2 * (v.x * v.x + v.y * v.y),
                                         -C2 * (v.z * v.z + v.w * v.w));
                } else {
                    sP[jp] = make_float4(0.f, 0.f, 0.f, 0.f);
                    sZ[jp] = make_float2(-1e4f, -1e4f);    // exp2 -> 0 in f16
                }
            }
            __syncthreads();

            unsigned hacc = 0u;
            #pragma unroll 16
            for (int jp = 0; jp < TPAIRS; jp++) {
                ulonglong2 pp = ((const ulonglong2*)sP)[jp];
                ull pz = ((const ull*)sZ)[jp];
                ull t;
                ADD2(t, pz, A2);
                FMA2(t, pp.y, qy2, t);
                FMA2(t, pp.x, qx2, t);
                float f0, f1;
                UPK2(f0, f1, t);
                unsigned h, e;
                asm("cvt.rn.f16x2.f32 %0, %1, %2;" : "=r"(h) : "f"(f1), "f"(f0));
                asm("ex2.approx.f16x2 %0, %1;" : "=r"(e) : "r"(h));
                asm("add.rn.f16x2 %0, %1, %2;" : "=r"(hacc) : "r"(hacc), "r"(e));
                if ((jp & 15) == 15) {   // compile-time under unroll 16
                    float g0, g1;
                    asm("{.reg .b16 lo,hi; mov.b32 {lo,hi}, %2;"
                        " cvt.f32.f16 %0, lo; cvt.f32.f16 %1, hi;}"
                        : "=f"(g0), "=f"(g1) : "r"(hacc));
                    a0 += g0; a1 += g1; hacc = 0u;
                }
            }
            __syncthreads();
        }
        if (act)
            g_ssum[((size_t)(z * 3 + ph) * NUM_BINS + bin) * NMC_CAP + qi] = a0 + a1;
    }

    // ---- phase 2: weighted KDE over batch (small), exact fp32 ----
    {
        const int np = B / 2;
        const int i0 = 2 * (int)(((long long)z * np) / DSPLIT);
        const int i1 = 2 * (int)(((long long)(z + 1) * np) / DSPLIT);
        float a0 = 0.f, a1 = 0.f;

        for (int base = i0; base < i1; base += TILE) {
            int m = min(TILE, i1 - base);
            for (int j = threadIdx.x; j < m; j += 128) {
                float dx = bx[(size_t)(base + j) * 2 + 0];
                float dy = bx[(size_t)(base + j) * 2 + 1];
                float wt = (y[base + j] == pred[base + j]) ? 1.f : 0.f;
                sd[j] = make_float4(Cm * dx, Cm * dy,
                                    -C2 * (dx * dx + dy * dy), wt);
            }
            __syncthreads();
            #pragma unroll 8
            for (int j = 0; j < m; j++) {
                float4 p = sd[j];
                float arg = fmaf(p.x, q.x, fmaf(p.y, q.y, p.z + A));
                float e = ex2_approx(arg);
                if (j & 1) a1 = fmaf(e, p.w, a1);
                else       a0 = fmaf(e, p.w, a0);
            }
            __syncthreads();
        }
        if (act)
            g_ssum[((size_t)(z * 3 + 2) * NUM_BINS + bin) * NMC_CAP + qi] = a0 + a1;
    }
}

// ---------------- K3: combine partials -> per-block v sums ----------------
__global__ void __launch_bounds__(128) combine_kernel(int NTRX, int NTEX, int B,
                                                      int NTR, int NTE)
{
    __shared__ float red[128];
    const int bin = blockIdx.y;
    const int cnt = g_qcnt[bin];
    const int qi  = blockIdx.x * 128 + threadIdx.x;

    float v = 0.f;
    if (qi < cnt) {
        float s0 = 0.f, s1 = 0.f, s2 = 0.f;
        #pragma unroll
        for (int zz = 0; zz < DSPLIT; zz++) {
            s0 += g_ssum[((size_t)(zz * 3 + 0) * NUM_BINS + bin) * NMC_CAP + qi];
            s1 += g_ssum[((size_t)(zz * 3 + 1) * NUM_BINS + bin) * NMC_CAP + qi];
            s2 += g_ssum[((size_t)(zz * 3 + 2) * NUM_BINS + bin) * NMC_CAP + qi];
        }
        int htr = 0, hte = 0;
        #pragma unroll
        for (int k = 0; k < HTR_B; k++) htr += g_hist_tr_p[k][bin];
        #pragma unroll
        for (int k = 0; k < HTE_B; k++) hte += g_hist_te_p[k][bin];
        float trr = (float)htr / (float)NTR;
        float ter = (float)hte / (float)NTE;
        float cntf = (float)g_correct;

        float kde_tr = s0 / ((float)NTRX * KN);
        float kde_te = s1 / ((float)NTEX * KN);
        float kde_w  = s2 / (fmaxf(cntf, 1.f) * KN);
        float p_y    = cntf / (float)B;

        float d_t = (ter > 0.f) ? (kde_te / ter) : 0.f;  // idx == 1 by construction
        float d_s = (trr > 0.f) ? (kde_tr / trr) : 0.f;

        float p_hs = kde_w * p_y / (kde_tr + 1e-8f);
        p_hs = fminf(fmaxf(p_hs, 0.f), 1.f);
        v = p_hs * (d_t - d_s);
    }

    red[threadIdx.x] = v; __syncthreads();
    for (int s = 64; s > 0; s >>= 1) {
        if (threadIdx.x < s) red[threadIdx.x] += red[threadIdx.x + s];
        __syncthreads();
    }
    if (threadIdx.x == 0)
        g_part[bin * QB_CAP + blockIdx.x] = red[0];
}

// ---------------- K4: final (one warp per bin, parallel) ----------------
__global__ void __launch_bounds__(NUM_BINS * 32) final_kernel(
    float* __restrict__ out, int nqb, int NMC, int NTE)
{
    __shared__ float sbin[NUM_BINS];
    const int bin  = threadIdx.x >> 5;
    const int lane = threadIdx.x & 31;

    float s = 0.f;
    for (int j = lane; j < nqb; j += 32) s += g_part[bin * QB_CAP + j];
    #pragma unroll
    for (int o = 16; o > 0; o >>= 1) s += __shfl_xor_sync(0xffffffff, s, o);

    if (lane == 0) {
        int hte = 0;
        #pragma unroll
        for (int k = 0; k < HTE_B; k++) hte += g_hist_te_p[k][bin];
        float ter = (float)hte / (float)NTE;
        float integral = (s / (float)NMC) * 100.0f;   // VOLUME
        sbin[bin] = (ter > 0.f) ? ter * fabsf(integral) : 0.f;
    }
    __syncthreads();
    if (threadIdx.x == 0) {
        float ec = 0.f;
        #pragma unroll
        for (int b = 0; b < NUM_BINS; b++) ec += sbin[b];
        out[0] = ec;
    }
}

// ---------------- launch ----------------
extern "C" void kernel_launch(void* const* d_in, const int* in_sizes, int n_in,
                              void* d_out, int out_size)
{
    const float* bx   = (const float*)d_in[0];
    const int*   y    = (const int*)  d_in[1];
    const int*   pred = (const int*)  d_in[2];
    const float* trp  = (const float*)d_in[3];
    const float* tep  = (const float*)d_in[4];
    const float* trx  = (const float*)d_in[5];
    const float* tex  = (const float*)d_in[6];
    const float* W    = (const float*)d_in[7];
    const float* bv   = (const float*)d_in[8];
    const float* mc   = (const float*)d_in[9];

    int B    = in_sizes[1];
    int NTR  = in_sizes[3];
    int NTE  = in_sizes[4];
    int NTRX = in_sizes[5] / 2;
    int NTEX = in_sizes[6] / 2;
    int NMC  = in_sizes[9] / (2 * NUM_BINS);
    int nqb  = (NMC + 127) / 128;

    prep_kernel<<<NUM_BINS + HTR_B + HTE_B + 1, 1024>>>(
        mc, W, bv, trp, tep, y, pred, NMC, NTR, NTE, B);

    dim3 mg(nqb, NUM_BINS, DSPLIT);
    main_kernel<<<mg, 128>>>(trx, tex, bx, y, pred, NTRX, NTEX, B);

    dim3 cg(nqb, NUM_BINS);
    combine_kernel<<<cg, 128>>>(NTRX, NTEX, B, NTR, NTE);

    final_kernel<<<1, NUM_BINS * 32>>>((float*)d_out, nqb, NMC, NTE);
}

// round 13
// speedup vs baseline: 1.3444x; 1.3444x over previous
#include <cuda_runtime.h>

#define NUM_BINS 15
#define NMC_CAP  10240
#define QB_CAP   80
#define DSPLIT   32
#define TILE     512          /* points per tile */
#define TPAIRS   (TILE / 2)
#define HTR_B    16
#define HTE_B    8

#define STEP (1.0f / 15.0f)
#define C2   (1.4426950408889634f / 0.18f)   /* log2e / (2*BW*BW) */
#define KN   (0.5654866776461628f)           /* 2*pi*BW*BW */

typedef unsigned long long ull;

// ---------------- device scratch ----------------
__device__ int    g_hist_tr_p[HTR_B][NUM_BINS];
__device__ int    g_hist_te_p[HTE_B][NUM_BINS];
__device__ int    g_correct;
__device__ int    g_qcnt[NUM_BINS];
__device__ float2 g_q[NUM_BINS * NMC_CAP];
// layout: [ (z*3 + ph)*NUM_BINS + bin ] * NMC_CAP + qi   (qi fastest: coalesced)
__device__ float  g_ssum[(size_t)DSPLIT * 3 * NUM_BINS * NMC_CAP];  // ~59 MB
__device__ float  g_part[NUM_BINS * QB_CAP];

// ---------------- packed helpers ----------------
#define ADD2(d, a, b)    asm("add.rn.f32x2 %0, %1, %2;"      : "=l"(d) : "l"(a), "l"(b))
#define FMA2(d, a, b, c) asm("fma.rn.f32x2 %0, %1, %2, %3;"  : "=l"(d) : "l"(a), "l"(b), "l"(c))
#define PK2(d, lo, hi)   asm("mov.b64 %0, {%1, %2};"         : "=l"(d) : "f"(lo), "f"(hi))
#define UPK2(lo, hi, s)  asm("mov.b64 {%0, %1}, %2;"         : "=f"(lo), "=f"(hi) : "l"(s))

__device__ __forceinline__ float ex2_approx(float x) {
    float r;
    asm("ex2.approx.ftz.f32 %0, %1;" : "=f"(r) : "f"(x));
    return r;
}

// hat_s = max softmax(x@W + b); membership in bin's [lo,hi] (inclusive)
__device__ __forceinline__ bool pass_bin(float qx, float qy,
                                         const float* __restrict__ W,
                                         const float* __restrict__ bv,
                                         int bin) {
    float l[10];
    float lmax = -1e30f;
    #pragma unroll
    for (int c = 0; c < 10; c++) {
        l[c] = fmaf(qx, W[c], fmaf(qy, W[10 + c], bv[c]));
        lmax = fmaxf(lmax, l[c]);
    }
    float s = 0.f;
    #pragma unroll
    for (int c = 0; c < 10; c++) s += __expf(l[c] - lmax);
    float hs = 1.f / s;
    float lo = bin * STEP;
    float hi = (bin + 1) * STEP;
    return (hs >= lo) && (hs <= hi);
}

// ---------------- K1: fused filter + hist partials + correct ----------------
__global__ void __launch_bounds__(1024) prep_kernel(
    const float* __restrict__ mc, const float* __restrict__ W,
    const float* __restrict__ bv,
    const float* __restrict__ trp, const float* __restrict__ tep,
    const int* __restrict__ y, const int* __restrict__ pred,
    int NMC, int NTR, int NTE, int B)
{
    const int part = blockIdx.x;
    const int tid  = threadIdx.x;

    if (part < NUM_BINS) {
        __shared__ int wtot[32];
        __shared__ int wbase[32];
        __shared__ int runbase;
        const int bin  = part;
        const int lane = tid & 31;
        const int wid  = tid >> 5;
        if (tid == 0) runbase = 0;
        __syncthreads();

        for (int base = 0; base < NMC; base += 1024) {
            int qi = base + tid;
            bool p = false;
            float qx = 0.f, qy = 0.f;
            if (qi < NMC) {
                qx = mc[(size_t)(bin * NMC + qi) * 2 + 0];
                qy = mc[(size_t)(bin * NMC + qi) * 2 + 1];
                p = pass_bin(qx, qy, W, bv, bin);
            }
            unsigned mask = __ballot_sync(0xffffffffu, p);
            int off = __popc(mask & ((1u << lane) - 1u));
            if (lane == 0) wtot[wid] = __popc(mask);
            __syncthreads();
            if (tid == 0) {
                int r = runbase;
                #pragma unroll
                for (int w = 0; w < 32; w++) { wbase[w] = r; r += wtot[w]; }
                runbase = r;
            }
            __syncthreads();
            if (p)
                g_q[bin * NMC_CAP + wbase[wid] + off] = make_float2(qx, qy);
            __syncthreads();
        }
        if (tid == 0) g_qcnt[bin] = runbase;
    } else if (part < NUM_BINS + HTR_B + HTE_B) {
        __shared__ int sh[NUM_BINS];
        if (tid < NUM_BINS) sh[tid] = 0;
        __syncthreads();
        bool is_tr = (part < NUM_BINS + HTR_B);
        const float* src = is_tr ? trp : tep;
        int n  = is_tr ? NTR : NTE;
        int nb = is_tr ? HTR_B : HTE_B;
        int pb = is_tr ? (part - NUM_BINS) : (part - NUM_BINS - HTR_B);
        for (int i = pb * 1024 + tid; i < n; i += nb * 1024) {
            float p = src[i];
            int bx = (int)ceilf(p * 15.f) - 1;
            bx = min(14, max(0, bx));
            if (!(p > bx * STEP && p <= (bx + 1) * STEP)) {
                if (p <= bx * STEP) bx--; else bx++;
            }
            if (bx >= 0 && bx < NUM_BINS && p > bx * STEP && p <= (bx + 1) * STEP)
                atomicAdd(&sh[bx], 1);
        }
        __syncthreads();
        if (tid < NUM_BINS) {
            if (is_tr) g_hist_tr_p[pb][tid] = sh[tid];
            else       g_hist_te_p[pb][tid] = sh[tid];
        }
    } else {
        __shared__ int red[1024];
        int c = 0;
        for (int i = tid; i < B; i += 1024)
            c += (y[i] == pred[i]) ? 1 : 0;
        red[tid] = c; __syncthreads();
        for (int s = 512; s > 0; s >>= 1) {
            if (tid < s) red[tid] += red[tid + s];
            __syncthreads();
        }
        if (tid == 0) g_correct = red[0];
    }
}

// ---------------- K2: KDE main (f16x2 EX2 for phases 0/1, fp32 for phase 2) --
__global__ void __launch_bounds__(128) main_kernel(
    const float* __restrict__ trx, const float* __restrict__ tex,
    const float* __restrict__ bx,
    const int* __restrict__ y, const int* __restrict__ pred,
    int NTRX, int NTEX, int B)
{
    __shared__ __align__(16) unsigned char sraw[TILE * 16];  // 8 KB, unioned
    float4* sP  = (float4*)sraw;                  // [TPAIRS] (cmx0,cmx1,cmy0,cmy1)
    float2* sZ  = (float2*)(sraw + TPAIRS * 16);  // [TPAIRS] (z0,z1)
    float4* sd  = (float4*)sraw;                  // phase-2 view [TILE]

    const int bin = blockIdx.y;
    const int z   = blockIdx.z;
    const int cnt = g_qcnt[bin];
    if ((int)(blockIdx.x * 128) >= cnt) return;

    const int  qi  = blockIdx.x * 128 + threadIdx.x;
    const bool act = qi < cnt;
    float2 q = act ? g_q[bin * NMC_CAP + qi] : make_float2(0.f, 0.f);

    const float Cm = 2.f * C2;
    const float A  = -C2 * (q.x * q.x + q.y * q.y);
    ull qx2, qy2, A2;
    PK2(qx2, q.x, q.x);
    PK2(qy2, q.y, q.y);
    PK2(A2,  A,   A);

    // ---- phases 0/1: unweighted KDE, f16x2 EX2 ----
    #pragma unroll 1
    for (int ph = 0; ph < 2; ph++) {
        const float* src = (ph == 0) ? trx : tex;
        const int    n   = (ph == 0) ? NTRX : NTEX;
        const int np = n / 2;
        const int p0 = (int)(((long long)z * np) / DSPLIT);
        const int p1 = (int)(((long long)(z + 1) * np) / DSPLIT);
        float a0 = 0.f, a1 = 0.f;

        for (int basep = p0; basep < p1; basep += TPAIRS) {
            int mp = min(TPAIRS, p1 - basep);
            for (int jp = threadIdx.x; jp < mp; jp += 128) {
                float4 v = ((const float4*)src)[basep + jp];  // (x0,y0,x1,y1)
                sP[jp] = make_float4(Cm * v.x, Cm * v.z, Cm * v.y, Cm * v.w);
                sZ[jp] = make_float2(-C2 * (v.x * v.x + v.y * v.y),
                                     -C2 * (v.z * v.z + v.w * v.w));
            }
            __syncthreads();

            unsigned hacc = 0u;
            #pragma unroll 16
            for (int jp = 0; jp < mp; jp++) {
                ulonglong2 pp = ((const ulonglong2*)sP)[jp];
                ull pz = ((const ull*)sZ)[jp];
                ull t;
                ADD2(t, pz, A2);
                FMA2(t, pp.y, qy2, t);
                FMA2(t, pp.x, qx2, t);
                float f0, f1;
                UPK2(f0, f1, t);
                unsigned h, e;
                asm("cvt.rn.f16x2.f32 %0, %1, %2;" : "=r"(h) : "f"(f1), "f"(f0));
                asm("ex2.approx.f16x2 %0, %1;" : "=r"(e) : "r"(h));
                asm("add.rn.f16x2 %0, %1, %2;" : "=r"(hacc) : "r"(hacc), "r"(e));
                if ((jp & 15) == 15) {
                    float g0, g1;
                    asm("{.reg .b16 lo,hi; mov.b32 {lo,hi}, %2;"
                        " cvt.f32.f16 %0, lo; cvt.f32.f16 %1, hi;}"
                        : "=f"(g0), "=f"(g1) : "r"(hacc));
                    a0 += g0; a1 += g1; hacc = 0u;
                }
            }
            {   // tail flush
                float g0, g1;
                asm("{.reg .b16 lo,hi; mov.b32 {lo,hi}, %2;"
                    " cvt.f32.f16 %0, lo; cvt.f32.f16 %1, hi;}"
                    : "=f"(g0), "=f"(g1) : "r"(hacc));
                a0 += g0; a1 += g1;
            }
            __syncthreads();
        }
        if (act)
            g_ssum[((size_t)(z * 3 + ph) * NUM_BINS + bin) * NMC_CAP + qi] = a0 + a1;
    }

    // ---- phase 2: weighted KDE over batch (small), exact fp32 ----
    {
        const int np = B / 2;
        const int i0 = 2 * (int)(((long long)z * np) / DSPLIT);
        const int i1 = 2 * (int)(((long long)(z + 1) * np) / DSPLIT);
        float a0 = 0.f, a1 = 0.f;

        for (int base = i0; base < i1; base += TILE) {
            int m = min(TILE, i1 - base);
            for (int j = threadIdx.x; j < m; j += 128) {
                float dx = bx[(size_t)(base + j) * 2 + 0];
                float dy = bx[(size_t)(base + j) * 2 + 1];
                float wt = (y[base + j] == pred[base + j]) ? 1.f : 0.f;
                sd[j] = make_float4(Cm * dx, Cm * dy,
                                    -C2 * (dx * dx + dy * dy), wt);
            }
            __syncthreads();
            #pragma unroll 8
            for (int j = 0; j < m; j++) {
                float4 p = sd[j];
                float arg = fmaf(p.x, q.x, fmaf(p.y, q.y, p.z + A));
                float e = ex2_approx(arg);
                if (j & 1) a1 = fmaf(e, p.w, a1);
                else       a0 = fmaf(e, p.w, a0);
            }
            __syncthreads();
        }
        if (act)
            g_ssum[((size_t)(z * 3 + 2) * NUM_BINS + bin) * NMC_CAP + qi] = a0 + a1;
    }
}

// ---------------- K3: combine partials -> per-block v sums ----------------
__global__ void __launch_bounds__(128) combine_kernel(int NTRX, int NTEX, int B,
                                                      int NTR, int NTE)
{
    __shared__ float red[128];
    const int bin = blockIdx.y;
    const int cnt = g_qcnt[bin];
    const int qi  = blockIdx.x * 128 + threadIdx.x;

    float v = 0.f;
    if (qi < cnt) {
        float s0 = 0.f, s1 = 0.f, s2 = 0.f;
        #pragma unroll
        for (int zz = 0; zz < DSPLIT; zz++) {
            s0 += g_ssum[((size_t)(zz * 3 + 0) * NUM_BINS + bin) * NMC_CAP + qi];
            s1 += g_ssum[((size_t)(zz * 3 + 1) * NUM_BINS + bin) * NMC_CAP + qi];
            s2 += g_ssum[((size_t)(zz * 3 + 2) * NUM_BINS + bin) * NMC_CAP + qi];
        }
        int htr = 0, hte = 0;
        #pragma unroll
        for (int k = 0; k < HTR_B; k++) htr += g_hist_tr_p[k][bin];
        #pragma unroll
        for (int k = 0; k < HTE_B; k++) hte += g_hist_te_p[k][bin];
        float trr = (float)htr / (float)NTR;
        float ter = (float)hte / (float)NTE;
        float cntf = (float)g_correct;

        float kde_tr = s0 / ((float)NTRX * KN);
        float kde_te = s1 / ((float)NTEX * KN);
        float kde_w  = s2 / (fmaxf(cntf, 1.f) * KN);
        float p_y    = cntf / (float)B;

        float d_t = (ter > 0.f) ? (kde_te / ter) : 0.f;  // idx == 1 by construction
        float d_s = (trr > 0.f) ? (kde_tr / trr) : 0.f;

        float p_hs = kde_w * p_y / (kde_tr + 1e-8f);
        p_hs = fminf(fmaxf(p_hs, 0.f), 1.f);
        v = p_hs * (d_t - d_s);
    }

    red[threadIdx.x] = v; __syncthreads();
    for (int s = 64; s > 0; s >>= 1) {
        if (threadIdx.x < s) red[threadIdx.x] += red[threadIdx.x + s];
        __syncthreads();
    }
    if (threadIdx.x == 0)
        g_part[bin * QB_CAP + blockIdx.x] = red[0];
}

// ---------------- K4: final (one warp per bin, parallel) ----------------
__global__ void __launch_bounds__(NUM_BINS * 32) final_kernel(
    float* __restrict__ out, int nqb, int NMC, int NTE)
{
    __shared__ float sbin[NUM_BINS];
    const int bin  = threadIdx.x >> 5;
    const int lane = threadIdx.x & 31;

    float s = 0.f;
    for (int j = lane; j < nqb; j += 32) s += g_part[bin * QB_CAP + j];
    #pragma unroll
    for (int o = 16; o > 0; o >>= 1) s += __shfl_xor_sync(0xffffffff, s, o);

    if (lane == 0) {
        int hte = 0;
        #pragma unroll
        for (int k = 0; k < HTE_B; k++) hte += g_hist_te_p[k][bin];
        float ter = (float)hte / (float)NTE;
        float integral = (s / (float)NMC) * 100.0f;   // VOLUME
        sbin[bin] = (ter > 0.f) ? ter * fabsf(integral) : 0.f;
    }
    __syncthreads();
    if (threadIdx.x == 0) {
        float ec = 0.f;
        #pragma unroll
        for (int b = 0; b < NUM_BINS; b++) ec += sbin[b];
        out[0] = ec;
    }
}

// ---------------- launch ----------------
extern "C" void kernel_launch(void* const* d_in, const int* in_sizes, int n_in,
                              void* d_out, int out_size)
{
    const float* bx   = (const float*)d_in[0];
    const int*   y    = (const int*)  d_in[1];
    const int*   pred = (const int*)  d_in[2];
    const float* trp  = (const float*)d_in[3];
    const float* tep  = (const float*)d_in[4];
    const float* trx  = (const float*)d_in[5];
    const float* tex  = (const float*)d_in[6];
    const float* W    = (const float*)d_in[7];
    const float* bv   = (const float*)d_in[8];
    const float* mc   = (const float*)d_in[9];

    int B    = in_sizes[1];
    int NTR  = in_sizes[3];
    int NTE  = in_sizes[4];
    int NTRX = in_sizes[5] / 2;
    int NTEX = in_sizes[6] / 2;
    int NMC  = in_sizes[9] / (2 * NUM_BINS);
    int nqb  = (NMC + 127) / 128;

    prep_kernel<<<NUM_BINS + HTR_B + HTE_B + 1, 1024>>>(
        mc, W, bv, trp, tep, y, pred, NMC, NTR, NTE, B);

    dim3 mg(nqb, NUM_BINS, DSPLIT);
    main_kernel<<<mg, 128>>>(trx, tex, bx, y, pred, NTRX, NTEX, B);

    dim3 cg(nqb, NUM_BINS);
    combine_kernel<<<cg, 128>>>(NTRX, NTEX, B, NTR, NTE);

    final_kernel<<<1, NUM_BINS * 32>>>((float*)d_out, nqb, NMC, NTE);
}